// round 3
// baseline (speedup 1.0000x reference)
#include <cuda_runtime.h>
#include <cuda_bf16.h>
#include <cstdint>

// ============================ helpers ============================
__device__ __forceinline__ uint32_t smem_u32(const void* p) {
    uint32_t a;
    asm("{ .reg .u64 t; cvta.to.shared.u64 t, %1; cvt.u32.u64 %0, t; }" : "=r"(a) : "l"(p));
    return a;
}
__device__ __forceinline__ uint32_t sw128(uint32_t o) { return o ^ ((o >> 3) & 0x70); }

#define LDSM_X4(r0, r1, r2, r3, a) \
    asm volatile("ldmatrix.sync.aligned.m8n8.x4.shared.b16 {%0,%1,%2,%3}, [%4];" \
                 : "=r"(r0), "=r"(r1), "=r"(r2), "=r"(r3) : "r"(a))

__device__ __forceinline__ void mma16816(float* c, const uint32_t* a, uint32_t b0, uint32_t b1) {
    asm volatile(
        "mma.sync.aligned.m16n8k16.row.col.f32.bf16.bf16.f32 "
        "{%0,%1,%2,%3}, {%4,%5,%6,%7}, {%8,%9}, {%0,%1,%2,%3};"
        : "+f"(c[0]), "+f"(c[1]), "+f"(c[2]), "+f"(c[3])
        : "r"(a[0]), "r"(a[1]), "r"(a[2]), "r"(a[3]), "r"(b0), "r"(b1));
}

// ============================ device scratch ============================
// W repacked: 12 chunk images, each [128 n-rows][64 bf16 k], SW128 swizzled, 16KB
__device__ __align__(16) unsigned char g_Wsw[12 * 16384];
// Normalized embeddings: 1056 row-tiles of 128 rows; per tile 2 chunk images
// (cols 0-63, 64-127), each [128 rows][64 bf16], SW128, 16KB.
// tiles 0..31 = Q (4096 rows), 32..543 = PD (65536), 544..1055 = ND (65536)
__device__ __align__(16) unsigned char g_norm[1056 * 32768];

// ============================ Kernel 0: W repack ============================
__global__ void k_wprep(const float* __restrict__ W) {
    int idx = blockIdx.x * 256 + threadIdx.x;   // 0 .. 98303
    int c = idx >> 13;                           // chunk (0..11)
    int rem = idx & 8191;
    int j = rem >> 7;                            // k within chunk (0..63)
    int n = rem & 127;                           // output dim
    float v = W[(c * 64 + j) * 128 + n];
    __nv_bfloat16 bv = __float2bfloat16(v);
    *(__nv_bfloat16*)(g_Wsw + c * 16384 + sw128((uint32_t)(n * 128 + j * 2))) = bv;
}

// ============================ Kernel 1: projection + bias + L2 norm ========
// grid 1056, block 256 (8 warps: 4 M x 2 N). Each CTA: M=128 rows, N=128, K=768.
// smem: [0..512) bias fp32, [512..1536) rowsq fp32[2][128],
//       [2048..18432) A tile (128r x 64k bf16 SW128), [18432..34816) B tile
__global__ void __launch_bounds__(256, 2) k_proj(
    const float* __restrict__ qh, const float* __restrict__ pdh, const float* __restrict__ ndh,
    const float* __restrict__ bias, const int* __restrict__ pdm, const int* __restrict__ ndm)
{
    extern __shared__ __align__(1024) unsigned char smem[];
    uint32_t sb = smem_u32(smem);
    const int tid = threadIdx.x, wid = tid >> 5, lid = tid & 31;
    const int wm = wid & 3, wn = wid >> 2;
    const int tg = lid & 3, gid = lid >> 2;
    const int t = blockIdx.x;

    const float* src; const int* mask; int r0;
    if (t < 32)       { src = qh  + (size_t)t * 98304;         mask = nullptr; r0 = 0; }
    else if (t < 544) { src = pdh + (size_t)(t - 32)  * 98304; mask = pdm;     r0 = (t - 32)  * 128; }
    else              { src = ndh + (size_t)(t - 544) * 98304; mask = ndm;     r0 = (t - 544) * 128; }

    if (tid < 128) ((float*)smem)[tid] = bias[tid];

    float c[2][8][4];
    #pragma unroll
    for (int mi = 0; mi < 2; ++mi)
        #pragma unroll
        for (int ni = 0; ni < 8; ++ni)
            #pragma unroll
            for (int r = 0; r < 4; ++r) c[mi][ni][r] = 0.f;

    const int lrow = (lid & 7) + ((lid >> 3) & 1) * 8;   // ldmatrix row within 16
    const int lhalf = lid >> 4;                           // ldmatrix k-half

    for (int it = 0; it < 12; ++it) {
        if (it) __syncthreads();
        // A tile: 128 rows x 64 fp32 -> bf16, SW128
        #pragma unroll
        for (int u = 0; u < 8; ++u) {
            int f = tid + u * 256;               // 0..2047
            int r = f >> 4, seg = f & 15;        // seg: 16 x 8B = 128B row
            float4 v = *(const float4*)(src + (size_t)r * 768 + it * 64 + seg * 4);
            __nv_bfloat162 lo = __floats2bfloat162_rn(v.x, v.y);
            __nv_bfloat162 hi = __floats2bfloat162_rn(v.z, v.w);
            uint2 pk; pk.x = *(uint32_t*)&lo; pk.y = *(uint32_t*)&hi;
            *(uint2*)(smem + 2048 + sw128((uint32_t)(r * 128 + seg * 8))) = pk;
        }
        // B tile: linear 16KB copy of pre-swizzled W chunk (L2-resident)
        {
            const uint4* wsrc = (const uint4*)(g_Wsw + it * 16384);
            uint4* wdst = (uint4*)(smem + 18432);
            #pragma unroll
            for (int u = 0; u < 4; ++u) wdst[tid + u * 256] = wsrc[tid + u * 256];
        }
        __syncthreads();

        #pragma unroll
        for (int ks = 0; ks < 4; ++ks) {
            const int lseg = (ks * 2 + lhalf) * 16;
            uint32_t af[2][4];
            #pragma unroll
            for (int mi = 0; mi < 2; ++mi) {
                int r = wm * 32 + mi * 16 + lrow;
                uint32_t a = sb + 2048 + sw128((uint32_t)(r * 128 + lseg));
                LDSM_X4(af[mi][0], af[mi][1], af[mi][2], af[mi][3], a);
            }
            uint32_t bf[8][2];
            #pragma unroll
            for (int nb = 0; nb < 4; ++nb) {
                int n = wn * 64 + nb * 16 + lrow;
                uint32_t a = sb + 18432 + sw128((uint32_t)(n * 128 + lseg));
                uint32_t q0, q1, q2, q3;
                LDSM_X4(q0, q1, q2, q3, a);
                bf[nb * 2][0] = q0; bf[nb * 2][1] = q2;
                bf[nb * 2 + 1][0] = q1; bf[nb * 2 + 1][1] = q3;
            }
            #pragma unroll
            for (int mi = 0; mi < 2; ++mi)
                #pragma unroll
                for (int ni = 0; ni < 8; ++ni)
                    mma16816(c[mi][ni], af[mi], bf[ni][0], bf[ni][1]);
        }
    }

    // ---------------- epilogue: bias, row sum-of-squares, normalize, store ---
    const float* bsm = (const float*)smem;
    float* rowsq = (float*)(smem + 512);
    #pragma unroll
    for (int mi = 0; mi < 2; ++mi)
        #pragma unroll
        for (int rp = 0; rp < 2; ++rp) {
            float s = 0.f;
            #pragma unroll
            for (int ni = 0; ni < 8; ++ni)
                #pragma unroll
                for (int c0 = 0; c0 < 2; ++c0) {
                    int col = wn * 64 + ni * 8 + tg * 2 + c0;
                    float x = c[mi][ni][rp * 2 + c0] + bsm[col];
                    c[mi][ni][rp * 2 + c0] = x;
                    s += x * x;
                }
            s += __shfl_xor_sync(0xFFFFFFFFu, s, 1);
            s += __shfl_xor_sync(0xFFFFFFFFu, s, 2);
            int row = wm * 32 + mi * 16 + gid + rp * 8;
            if (tg == 0) rowsq[wn * 128 + row] = s;
        }
    __syncthreads();

    unsigned char* dst = g_norm + (size_t)t * 32768 + (size_t)wn * 16384;
    #pragma unroll
    for (int mi = 0; mi < 2; ++mi)
        #pragma unroll
        for (int rp = 0; rp < 2; ++rp) {
            int row = wm * 32 + mi * 16 + gid + rp * 8;
            float tot = rowsq[row] + rowsq[128 + row];
            float mf = mask ? (float)mask[r0 + row] : 1.f;
            float sc = mf / fmaxf(sqrtf(tot), 1e-12f);
            #pragma unroll
            for (int ni = 0; ni < 8; ++ni) {
                float x0 = c[mi][ni][rp * 2]     * sc;
                float x1 = c[mi][ni][rp * 2 + 1] * sc;
                __nv_bfloat162 p2 = __floats2bfloat162_rn(x0, x1);
                *(uint32_t*)(dst + sw128((uint32_t)(row * 128 + (ni * 8 + tg * 2) * 2))) =
                    *(uint32_t*)&p2;
            }
        }
}

// ============================ Kernel 2: MaxSim ============================
// grid 256 (= batch*2 pos/neg), block 128 (4 warps, each 32 doc rows).
// smem: [0..512) reduce buf fp32[4][32],
//       [1024..9216) Q tile: 2 chunks x [32r x 64k] SW128 (4KB each),
//       [9216..41984) doc tile: 2 chunks x [128r x 64k] SW128 (16KB each)
__global__ void __launch_bounds__(128) k_maxsim(float* __restrict__ out)
{
    extern __shared__ __align__(1024) unsigned char smem[];
    uint32_t sb = smem_u32(smem);
    const int tid = threadIdx.x, wid = tid >> 5, lid = tid & 31;
    const int tg = lid & 3;
    const int b = blockIdx.x >> 1, s = blockIdx.x & 1;
    const int tbase = (s ? 544 : 32) + b * 4;

    // Q slice: tile b>>2, rows (b&3)*32 (row-aligned to 8 -> sub-image stays valid SW128)
    {
        const unsigned char* qsrc = g_norm + (size_t)(b >> 2) * 32768 + (size_t)(b & 3) * 4096;
        #pragma unroll
        for (int ch = 0; ch < 2; ++ch) {
            const uint4* sp = (const uint4*)(qsrc + ch * 16384);
            uint4* dp = (uint4*)(smem + 1024 + ch * 4096);
            #pragma unroll
            for (int u = 0; u < 2; ++u) dp[tid + u * 128] = sp[tid + u * 128];
        }
    }

    const int lrow = (lid & 7) + ((lid >> 3) & 1) * 8;
    const int lhalf = lid >> 4;

    float vmax[2][4][4];
    #pragma unroll
    for (int mi = 0; mi < 2; ++mi)
        #pragma unroll
        for (int ni = 0; ni < 4; ++ni)
            #pragma unroll
            for (int r = 0; r < 4; ++r) vmax[mi][ni][r] = -3.0e38f;

    for (int i = 0; i < 4; ++i) {
        if (i) __syncthreads();
        // doc tile i: 32KB linear copy of two pre-swizzled chunk images
        {
            const uint4* sp = (const uint4*)(g_norm + (size_t)(tbase + i) * 32768);
            uint4* dp = (uint4*)(smem + 9216);
            #pragma unroll
            for (int u = 0; u < 16; ++u) dp[tid + u * 128] = sp[tid + u * 128];
        }
        __syncthreads();

        float cc[2][4][4];
        #pragma unroll
        for (int mi = 0; mi < 2; ++mi)
            #pragma unroll
            for (int ni = 0; ni < 4; ++ni)
                #pragma unroll
                for (int r = 0; r < 4; ++r) cc[mi][ni][r] = 0.f;

        #pragma unroll
        for (int ks = 0; ks < 8; ++ks) {
            const int chunk = ks >> 2, kk = ks & 3;
            const int lseg = (kk * 2 + lhalf) * 16;
            uint32_t af[2][4];
            #pragma unroll
            for (int mi = 0; mi < 2; ++mi) {
                int r = wid * 32 + mi * 16 + lrow;
                uint32_t a = sb + 9216 + chunk * 16384 + sw128((uint32_t)(r * 128 + lseg));
                LDSM_X4(af[mi][0], af[mi][1], af[mi][2], af[mi][3], a);
            }
            uint32_t bf[4][2];
            #pragma unroll
            for (int nb = 0; nb < 2; ++nb) {
                int n = nb * 16 + lrow;
                uint32_t a = sb + 1024 + chunk * 4096 + sw128((uint32_t)(n * 128 + lseg));
                uint32_t q0, q1, q2, q3;
                LDSM_X4(q0, q1, q2, q3, a);
                bf[nb * 2][0] = q0; bf[nb * 2][1] = q2;
                bf[nb * 2 + 1][0] = q1; bf[nb * 2 + 1][1] = q3;
            }
            #pragma unroll
            for (int mi = 0; mi < 2; ++mi)
                #pragma unroll
                for (int ni = 0; ni < 4; ++ni)
                    mma16816(cc[mi][ni], af[mi], bf[ni][0], bf[ni][1]);
        }
        #pragma unroll
        for (int mi = 0; mi < 2; ++mi)
            #pragma unroll
            for (int ni = 0; ni < 4; ++ni)
                #pragma unroll
                for (int r = 0; r < 4; ++r)
                    vmax[mi][ni][r] = fmaxf(vmax[mi][ni][r], cc[mi][ni][r]);
    }

    // per-column max over this warp's 32 doc rows
    float colmax[4][2];
    #pragma unroll
    for (int ni = 0; ni < 4; ++ni)
        #pragma unroll
        for (int c0 = 0; c0 < 2; ++c0) {
            float m = fmaxf(fmaxf(vmax[0][ni][c0], vmax[0][ni][c0 + 2]),
                            fmaxf(vmax[1][ni][c0], vmax[1][ni][c0 + 2]));
            m = fmaxf(m, __shfl_xor_sync(0xFFFFFFFFu, m, 4));
            m = fmaxf(m, __shfl_xor_sync(0xFFFFFFFFu, m, 8));
            m = fmaxf(m, __shfl_xor_sync(0xFFFFFFFFu, m, 16));
            colmax[ni][c0] = m;
        }
    float* red = (float*)smem;
    if (lid < 4) {
        #pragma unroll
        for (int ni = 0; ni < 4; ++ni)
            #pragma unroll
            for (int c0 = 0; c0 < 2; ++c0)
                red[wid * 32 + ni * 8 + lid * 2 + c0] = colmax[ni][c0];
    }
    __syncthreads();
    if (tid < 32) {
        float m = fmaxf(fmaxf(red[tid], red[32 + tid]), fmaxf(red[64 + tid], red[96 + tid]));
        #pragma unroll
        for (int off = 16; off; off >>= 1) m += __shfl_xor_sync(0xFFFFFFFFu, m, off);
        if (tid == 0) out[b * 2 + s] = m;
    }
}

// ============================ launch ============================
extern "C" void kernel_launch(void* const* d_in, const int* in_sizes, int n_in,
                              void* d_out, int out_size) {
    const float* qh  = (const float*)d_in[0];
    const float* pdh = (const float*)d_in[1];
    const float* ndh = (const float*)d_in[2];
    const float* W   = (const float*)d_in[3];
    const float* b   = (const float*)d_in[4];
    const int*   pdm = (const int*)d_in[5];
    const int*   ndm = (const int*)d_in[6];
    float* out = (float*)d_out;

    k_wprep<<<384, 256>>>(W);
    k_proj<<<1056, 256, 34816>>>(qh, pdh, ndh, b, pdm, ndm);
    k_maxsim<<<256, 128, 41984>>>(out);
}

// round 4
// speedup vs baseline: 1.1086x; 1.1086x over previous
#include <cuda_runtime.h>
#include <cuda_bf16.h>
#include <cstdint>

// ============================ helpers ============================
__device__ __forceinline__ uint32_t smem_u32(const void* p) {
    uint32_t a;
    asm("{ .reg .u64 t; cvta.to.shared.u64 t, %1; cvt.u32.u64 %0, t; }" : "=r"(a) : "l"(p));
    return a;
}
__device__ __forceinline__ uint32_t sw128(uint32_t o) { return o ^ ((o >> 3) & 0x70); }

#define LDSM_X4(r0, r1, r2, r3, a) \
    asm volatile("ldmatrix.sync.aligned.m8n8.x4.shared.b16 {%0,%1,%2,%3}, [%4];" \
                 : "=r"(r0), "=r"(r1), "=r"(r2), "=r"(r3) : "r"(a))

#define CP_ASYNC16(dst, src) \
    asm volatile("cp.async.cg.shared.global [%0], [%1], 16;" :: "r"(dst), "l"(src))
#define CP_COMMIT() asm volatile("cp.async.commit_group;")
#define CP_WAIT0()  asm volatile("cp.async.wait_group 0;")

__device__ __forceinline__ void mma16816(float* c, const uint32_t* a, uint32_t b0, uint32_t b1) {
    asm volatile(
        "mma.sync.aligned.m16n8k16.row.col.f32.bf16.bf16.f32 "
        "{%0,%1,%2,%3}, {%4,%5,%6,%7}, {%8,%9}, {%0,%1,%2,%3};"
        : "+f"(c[0]), "+f"(c[1]), "+f"(c[2]), "+f"(c[3])
        : "r"(a[0]), "r"(a[1]), "r"(a[2]), "r"(a[3]), "r"(b0), "r"(b1));
}

// ============================ device scratch ============================
// W repacked: 12 chunk images, each [128 n-rows][64 bf16 k], SW128 swizzled, 16KB
__device__ __align__(16) unsigned char g_Wsw[12 * 16384];
// Normalized embeddings: 1056 row-tiles of 128 rows; per tile 2 chunk images
// (cols 0-63, 64-127), each [128 rows][64 bf16], SW128, 16KB.
// tiles 0..31 = Q (4096 rows), 32..543 = PD (65536), 544..1055 = ND (65536)
__device__ __align__(16) unsigned char g_norm[1056 * 32768];

// ============================ Kernel 0: W repack ============================
__global__ void k_wprep(const float* __restrict__ W) {
    int idx = blockIdx.x * 256 + threadIdx.x;   // 0 .. 98303
    int c = idx >> 13;                           // chunk (0..11)
    int rem = idx & 8191;
    int j = rem >> 7;                            // k within chunk (0..63)
    int n = rem & 127;                           // output dim
    float v = W[(c * 64 + j) * 128 + n];
    __nv_bfloat16 bv = __float2bfloat16(v);
    *(__nv_bfloat16*)(g_Wsw + c * 16384 + sw128((uint32_t)(n * 128 + j * 2))) = bv;
}

// ============================ Kernel 1: projection + bias + L2 norm ========
// grid 1056, block 256 (8 warps: 4 M x 2 N). Each CTA: M=128 rows, N=128, K=768.
// Double-buffered pipeline: A via register prefetch (LDG overlapped with MMA),
// B via cp.async from L2-resident pre-swizzled W.
// smem: [0..512) bias fp32, [512..1536) rowsq fp32[2][128],
//       [2048) A buf0 16KB, [18432) A buf1, [34816) B buf0 16KB, [51200) B buf1
__global__ void __launch_bounds__(256) k_proj(
    const float* __restrict__ qh, const float* __restrict__ pdh, const float* __restrict__ ndh,
    const float* __restrict__ bias, const int* __restrict__ pdm, const int* __restrict__ ndm)
{
    extern __shared__ __align__(1024) unsigned char smem[];
    uint32_t sb = smem_u32(smem);
    const int tid = threadIdx.x, wid = tid >> 5, lid = tid & 31;
    const int wm = wid & 3, wn = wid >> 2;
    const int tg = lid & 3, gid = lid >> 2;
    const int t = blockIdx.x;

    const float* src; const int* mask; int r0;
    if (t < 32)       { src = qh  + (size_t)t * 98304;         mask = nullptr; r0 = 0; }
    else if (t < 544) { src = pdh + (size_t)(t - 32)  * 98304; mask = pdm;     r0 = (t - 32)  * 128; }
    else              { src = ndh + (size_t)(t - 544) * 98304; mask = ndm;     r0 = (t - 544) * 128; }

    if (tid < 128) ((float*)smem)[tid] = bias[tid];

    float c[2][8][4];
    #pragma unroll
    for (int mi = 0; mi < 2; ++mi)
        #pragma unroll
        for (int ni = 0; ni < 8; ++ni)
            #pragma unroll
            for (int r = 0; r < 4; ++r) c[mi][ni][r] = 0.f;

    const int lrow = (lid & 7) + ((lid >> 3) & 1) * 8;   // ldmatrix row within 16
    const int lhalf = lid >> 4;                           // ldmatrix k-half
    const int fr = tid >> 4, fseg = tid & 15;             // A-load row / 16B-segment

    // prologue: B chunk 0 via cp.async, A chunk 0 into registers
    {
        uint32_t bdst = sb + 34816;
        const unsigned char* bsrc = g_Wsw;
        #pragma unroll
        for (int u = 0; u < 4; ++u)
            CP_ASYNC16(bdst + (tid + u * 256) * 16, bsrc + (size_t)(tid + u * 256) * 16);
        CP_COMMIT();
    }
    float4 areg[8];
    #pragma unroll
    for (int u = 0; u < 8; ++u)
        areg[u] = *(const float4*)(src + (size_t)(fr + u * 16) * 768 + fseg * 4);

    for (int it = 0; it < 12; ++it) {
        const int buf = it & 1;
        const uint32_t Ao = 2048 + buf * 16384;
        // store prefetched A regs -> smem (bf16, SW128)
        #pragma unroll
        for (int u = 0; u < 8; ++u) {
            __nv_bfloat162 lo = __floats2bfloat162_rn(areg[u].x, areg[u].y);
            __nv_bfloat162 hi = __floats2bfloat162_rn(areg[u].z, areg[u].w);
            uint2 pk; pk.x = *(uint32_t*)&lo; pk.y = *(uint32_t*)&hi;
            *(uint2*)(smem + Ao + sw128((uint32_t)((fr + u * 16) * 128 + fseg * 8))) = pk;
        }
        CP_WAIT0();            // B(it) landed
        __syncthreads();       // A stores + B visible to all; all MMA(it-1) reads done
        if (it < 11) {
            // stream B(it+1) into the other buffer (overlaps with MMA below)
            uint32_t bdst = sb + 34816 + (buf ^ 1) * 16384;
            const unsigned char* bsrc = g_Wsw + (size_t)(it + 1) * 16384;
            #pragma unroll
            for (int u = 0; u < 4; ++u)
                CP_ASYNC16(bdst + (tid + u * 256) * 16, bsrc + (size_t)(tid + u * 256) * 16);
            CP_COMMIT();
            // prefetch A(it+1) into registers (LDG latency hidden by MMA)
            #pragma unroll
            for (int u = 0; u < 8; ++u)
                areg[u] = *(const float4*)(src + (size_t)(fr + u * 16) * 768 + (it + 1) * 64 + fseg * 4);
        }
        // MMA on buf
        const uint32_t Ab = sb + Ao, Bb = sb + 34816 + buf * 16384;
        #pragma unroll
        for (int ks = 0; ks < 4; ++ks) {
            const int lseg = (ks * 2 + lhalf) * 16;
            uint32_t af[2][4];
            #pragma unroll
            for (int mi = 0; mi < 2; ++mi) {
                int r = wm * 32 + mi * 16 + lrow;
                LDSM_X4(af[mi][0], af[mi][1], af[mi][2], af[mi][3],
                        Ab + sw128((uint32_t)(r * 128 + lseg)));
            }
            uint32_t bf[8][2];
            #pragma unroll
            for (int nb = 0; nb < 4; ++nb) {
                int n = wn * 64 + nb * 16 + lrow;
                uint32_t q0, q1, q2, q3;
                LDSM_X4(q0, q1, q2, q3, Bb + sw128((uint32_t)(n * 128 + lseg)));
                bf[nb * 2][0] = q0; bf[nb * 2][1] = q2;
                bf[nb * 2 + 1][0] = q1; bf[nb * 2 + 1][1] = q3;
            }
            #pragma unroll
            for (int mi = 0; mi < 2; ++mi)
                #pragma unroll
                for (int ni = 0; ni < 8; ++ni)
                    mma16816(c[mi][ni], af[mi], bf[ni][0], bf[ni][1]);
        }
    }

    // ---------------- epilogue: bias, row sum-of-squares, normalize, store ---
    const float* bsm = (const float*)smem;
    float* rowsq = (float*)(smem + 512);
    #pragma unroll
    for (int mi = 0; mi < 2; ++mi)
        #pragma unroll
        for (int rp = 0; rp < 2; ++rp) {
            float s = 0.f;
            #pragma unroll
            for (int ni = 0; ni < 8; ++ni)
                #pragma unroll
                for (int c0 = 0; c0 < 2; ++c0) {
                    int col = wn * 64 + ni * 8 + tg * 2 + c0;
                    float x = c[mi][ni][rp * 2 + c0] + bsm[col];
                    c[mi][ni][rp * 2 + c0] = x;
                    s += x * x;
                }
            s += __shfl_xor_sync(0xFFFFFFFFu, s, 1);
            s += __shfl_xor_sync(0xFFFFFFFFu, s, 2);
            int row = wm * 32 + mi * 16 + gid + rp * 8;
            if (tg == 0) rowsq[wn * 128 + row] = s;
        }
    __syncthreads();

    unsigned char* dst = g_norm + (size_t)t * 32768 + (size_t)wn * 16384;
    #pragma unroll
    for (int mi = 0; mi < 2; ++mi)
        #pragma unroll
        for (int rp = 0; rp < 2; ++rp) {
            int row = wm * 32 + mi * 16 + gid + rp * 8;
            float tot = rowsq[row] + rowsq[128 + row];
            float mf = mask ? (float)mask[r0 + row] : 1.f;
            float sc = mf / fmaxf(sqrtf(tot), 1e-12f);
            #pragma unroll
            for (int ni = 0; ni < 8; ++ni) {
                float x0 = c[mi][ni][rp * 2]     * sc;
                float x1 = c[mi][ni][rp * 2 + 1] * sc;
                __nv_bfloat162 p2 = __floats2bfloat162_rn(x0, x1);
                *(uint32_t*)(dst + sw128((uint32_t)(row * 128 + (ni * 8 + tg * 2) * 2))) =
                    *(uint32_t*)&p2;
            }
        }
}

// ============================ Kernel 2: MaxSim ============================
// grid 256 (= batch*2 pos/neg), block 128 (4 warps, each 32 doc rows).
// Doc tiles double-buffered via cp.async.
// smem: [0..512) reduce buf fp32[4][32],
//       [1024..9216) Q tile: 2 chunks x [32r x 64k] SW128 (4KB each),
//       [9216) doc buf0 (2 x 16KB chunk images), [41984) doc buf1
__global__ void __launch_bounds__(128) k_maxsim(float* __restrict__ out)
{
    extern __shared__ __align__(1024) unsigned char smem[];
    uint32_t sb = smem_u32(smem);
    const int tid = threadIdx.x, wid = tid >> 5, lid = tid & 31;
    const int b = blockIdx.x >> 1, s = blockIdx.x & 1;
    const int tbase = (s ? 544 : 32) + b * 4;

    // prologue: doc tile 0 via cp.async
    {
        uint32_t dd = sb + 9216;
        const unsigned char* ds = g_norm + (size_t)tbase * 32768;
        #pragma unroll
        for (int u = 0; u < 16; ++u)
            CP_ASYNC16(dd + (tid + u * 128) * 16, ds + (size_t)(tid + u * 128) * 16);
        CP_COMMIT();
    }
    // Q slice: tile b>>2, rows (b&3)*32 (row-aligned to 8 -> valid SW128 sub-image)
    {
        const unsigned char* qsrc = g_norm + (size_t)(b >> 2) * 32768 + (size_t)(b & 3) * 4096;
        #pragma unroll
        for (int ch = 0; ch < 2; ++ch) {
            const uint4* sp = (const uint4*)(qsrc + ch * 16384);
            uint4* dp = (uint4*)(smem + 1024 + ch * 4096);
            #pragma unroll
            for (int u = 0; u < 2; ++u) dp[tid + u * 128] = sp[tid + u * 128];
        }
    }

    const int lrow = (lid & 7) + ((lid >> 3) & 1) * 8;
    const int lhalf = lid >> 4;

    float vmax[2][4][4];
    #pragma unroll
    for (int mi = 0; mi < 2; ++mi)
        #pragma unroll
        for (int ni = 0; ni < 4; ++ni)
            #pragma unroll
            for (int r = 0; r < 4; ++r) vmax[mi][ni][r] = -3.0e38f;

    for (int i = 0; i < 4; ++i) {
        const int buf = i & 1;
        CP_WAIT0();
        __syncthreads();
        if (i < 3) {
            uint32_t dd = sb + 9216 + (buf ^ 1) * 32768;
            const unsigned char* ds = g_norm + (size_t)(tbase + i + 1) * 32768;
            #pragma unroll
            for (int u = 0; u < 16; ++u)
                CP_ASYNC16(dd + (tid + u * 128) * 16, ds + (size_t)(tid + u * 128) * 16);
            CP_COMMIT();
        }

        float cc[2][4][4];
        #pragma unroll
        for (int mi = 0; mi < 2; ++mi)
            #pragma unroll
            for (int ni = 0; ni < 4; ++ni)
                #pragma unroll
                for (int r = 0; r < 4; ++r) cc[mi][ni][r] = 0.f;

        const uint32_t Db = sb + 9216 + buf * 32768;
        #pragma unroll
        for (int ks = 0; ks < 8; ++ks) {
            const int chunk = ks >> 2, kk = ks & 3;
            const int lseg = (kk * 2 + lhalf) * 16;
            uint32_t af[2][4];
            #pragma unroll
            for (int mi = 0; mi < 2; ++mi) {
                int r = wid * 32 + mi * 16 + lrow;
                LDSM_X4(af[mi][0], af[mi][1], af[mi][2], af[mi][3],
                        Db + chunk * 16384 + sw128((uint32_t)(r * 128 + lseg)));
            }
            uint32_t bf[4][2];
            #pragma unroll
            for (int nb = 0; nb < 2; ++nb) {
                int n = nb * 16 + lrow;
                uint32_t q0, q1, q2, q3;
                LDSM_X4(q0, q1, q2, q3,
                        sb + 1024 + chunk * 4096 + sw128((uint32_t)(n * 128 + lseg)));
                bf[nb * 2][0] = q0; bf[nb * 2][1] = q2;
                bf[nb * 2 + 1][0] = q1; bf[nb * 2 + 1][1] = q3;
            }
            #pragma unroll
            for (int mi = 0; mi < 2; ++mi)
                #pragma unroll
                for (int ni = 0; ni < 4; ++ni)
                    mma16816(cc[mi][ni], af[mi], bf[ni][0], bf[ni][1]);
        }
        #pragma unroll
        for (int mi = 0; mi < 2; ++mi)
            #pragma unroll
            for (int ni = 0; ni < 4; ++ni)
                #pragma unroll
                for (int r = 0; r < 4; ++r)
                    vmax[mi][ni][r] = fmaxf(vmax[mi][ni][r], cc[mi][ni][r]);
    }

    // per-column max over this warp's 32 doc rows
    float colmax[4][2];
    #pragma unroll
    for (int ni = 0; ni < 4; ++ni)
        #pragma unroll
        for (int c0 = 0; c0 < 2; ++c0) {
            float m = fmaxf(fmaxf(vmax[0][ni][c0], vmax[0][ni][c0 + 2]),
                            fmaxf(vmax[1][ni][c0], vmax[1][ni][c0 + 2]));
            m = fmaxf(m, __shfl_xor_sync(0xFFFFFFFFu, m, 4));
            m = fmaxf(m, __shfl_xor_sync(0xFFFFFFFFu, m, 8));
            m = fmaxf(m, __shfl_xor_sync(0xFFFFFFFFu, m, 16));
            colmax[ni][c0] = m;
        }
    float* red = (float*)smem;
    if (lid < 4) {
        #pragma unroll
        for (int ni = 0; ni < 4; ++ni)
            #pragma unroll
            for (int c0 = 0; c0 < 2; ++c0)
                red[wid * 32 + ni * 8 + lid * 2 + c0] = colmax[ni][c0];
    }
    __syncthreads();
    if (tid < 32) {
        float m = fmaxf(fmaxf(red[tid], red[32 + tid]), fmaxf(red[64 + tid], red[96 + tid]));
        #pragma unroll
        for (int off = 16; off; off >>= 1) m += __shfl_xor_sync(0xFFFFFFFFu, m, off);
        if (tid == 0) out[b * 2 + s] = m;
    }
}

// ============================ launch ============================
extern "C" void kernel_launch(void* const* d_in, const int* in_sizes, int n_in,
                              void* d_out, int out_size) {
    const float* qh  = (const float*)d_in[0];
    const float* pdh = (const float*)d_in[1];
    const float* ndh = (const float*)d_in[2];
    const float* W   = (const float*)d_in[3];
    const float* b   = (const float*)d_in[4];
    const int*   pdm = (const int*)d_in[5];
    const int*   ndm = (const int*)d_in[6];
    float* out = (float*)d_out;

    // dyn smem > 48KB needs an explicit opt-in (host attribute set, not a stream op)
    cudaFuncSetAttribute(k_proj,   cudaFuncAttributeMaxDynamicSharedMemorySize, 67584);
    cudaFuncSetAttribute(k_maxsim, cudaFuncAttributeMaxDynamicSharedMemorySize, 74752);

    k_wprep<<<384, 256>>>(W);
    k_proj<<<1056, 256, 67584>>>(qh, pdh, ndh, b, pdm, ndm);
    k_maxsim<<<256, 128, 74752>>>(out);
}

// round 5
// speedup vs baseline: 1.1096x; 1.0009x over previous
#include <cuda_runtime.h>
#include <cuda_bf16.h>
#include <cstdint>

// ============================ helpers ============================
__device__ __forceinline__ uint32_t smem_u32(const void* p) {
    uint32_t a;
    asm("{ .reg .u64 t; cvta.to.shared.u64 t, %1; cvt.u32.u64 %0, t; }" : "=r"(a) : "l"(p));
    return a;
}
__device__ __forceinline__ uint32_t sw128(uint32_t o) { return o ^ ((o >> 3) & 0x70); }

#define LDSM_X4(r0, r1, r2, r3, a) \
    asm volatile("ldmatrix.sync.aligned.m8n8.x4.shared.b16 {%0,%1,%2,%3}, [%4];" \
                 : "=r"(r0), "=r"(r1), "=r"(r2), "=r"(r3) : "r"(a))

#define CP_ASYNC16(dst, src) \
    asm volatile("cp.async.cg.shared.global [%0], [%1], 16;" :: "r"(dst), "l"(src))
#define CP_COMMIT() asm volatile("cp.async.commit_group;")
#define CP_WAIT0()  asm volatile("cp.async.wait_group 0;")

__device__ __forceinline__ void mma16816(float* c, const uint32_t* a, uint32_t b0, uint32_t b1) {
    asm volatile(
        "mma.sync.aligned.m16n8k16.row.col.f32.bf16.bf16.f32 "
        "{%0,%1,%2,%3}, {%4,%5,%6,%7}, {%8,%9}, {%0,%1,%2,%3};"
        : "+f"(c[0]), "+f"(c[1]), "+f"(c[2]), "+f"(c[3])
        : "r"(a[0]), "r"(a[1]), "r"(a[2]), "r"(a[3]), "r"(b0), "r"(b1));
}

// ============================ device scratch ============================
// W repacked: 12 chunk images, each [128 n-rows][64 bf16 k], SW128 swizzled, 16KB
__device__ __align__(16) unsigned char g_Wsw[12 * 16384];
// Normalized embeddings: 1056 row-tiles of 128 rows; per tile 2 chunk images
// (cols 0-63, 64-127), each [128 rows][64 bf16], SW128, 16KB.
// tiles 0..31 = Q (4096 rows), 32..543 = PD (65536), 544..1055 = ND (65536)
__device__ __align__(16) unsigned char g_norm[1056 * 32768];

// ============================ Kernel 0: W repack ============================
__global__ void k_wprep(const float* __restrict__ W) {
    int idx = blockIdx.x * 256 + threadIdx.x;   // 0 .. 98303
    int c = idx >> 13;                           // chunk (0..11)
    int rem = idx & 8191;
    int j = rem >> 7;                            // k within chunk (0..63)
    int n = rem & 127;                           // output dim
    float v = W[(c * 64 + j) * 128 + n];
    __nv_bfloat16 bv = __float2bfloat16(v);
    *(__nv_bfloat16*)(g_Wsw + c * 16384 + sw128((uint32_t)(n * 128 + j * 2))) = bv;
}

// ============================ Kernel 1: projection + bias + L2 norm ========
// grid 1056, block 256 (8 warps: 4 M x 2 N). Each CTA: M=128 rows, N=128, K=768.
// Double-buffered pipeline: A via register prefetch (LDG overlapped with MMA),
// B via cp.async from L2-resident pre-swizzled W.
// smem: [0..512) bias fp32, [512..1536) rowsq fp32[2][128],
//       [2048) A buf0 16KB, [18432) A buf1, [34816) B buf0 16KB, [51200) B buf1
__global__ void __launch_bounds__(256) k_proj(
    const float* __restrict__ qh, const float* __restrict__ pdh, const float* __restrict__ ndh,
    const float* __restrict__ bias, const int* __restrict__ pdm, const int* __restrict__ ndm)
{
    extern __shared__ __align__(1024) unsigned char smem[];
    uint32_t sb = smem_u32(smem);
    const int tid = threadIdx.x, wid = tid >> 5, lid = tid & 31;
    const int wm = wid & 3, wn = wid >> 2;
    const int tg = lid & 3, gid = lid >> 2;
    const int t = blockIdx.x;

    const float* src; const int* mask; int r0;
    if (t < 32)       { src = qh  + (size_t)t * 98304;         mask = nullptr; r0 = 0; }
    else if (t < 544) { src = pdh + (size_t)(t - 32)  * 98304; mask = pdm;     r0 = (t - 32)  * 128; }
    else              { src = ndh + (size_t)(t - 544) * 98304; mask = ndm;     r0 = (t - 544) * 128; }

    if (tid < 128) ((float*)smem)[tid] = bias[tid];

    float c[2][8][4];
    #pragma unroll
    for (int mi = 0; mi < 2; ++mi)
        #pragma unroll
        for (int ni = 0; ni < 8; ++ni)
            #pragma unroll
            for (int r = 0; r < 4; ++r) c[mi][ni][r] = 0.f;

    const int lrow = (lid & 7) + ((lid >> 3) & 1) * 8;   // ldmatrix row within 16
    const int lhalf = lid >> 4;                           // ldmatrix k-half
    const int fr = tid >> 4, fseg = tid & 15;             // A-load row / 16B-segment

    // prologue: B chunk 0 via cp.async, A chunk 0 into registers
    {
        uint32_t bdst = sb + 34816;
        const unsigned char* bsrc = g_Wsw;
        #pragma unroll
        for (int u = 0; u < 4; ++u)
            CP_ASYNC16(bdst + (tid + u * 256) * 16, bsrc + (size_t)(tid + u * 256) * 16);
        CP_COMMIT();
    }
    float4 areg[8];
    #pragma unroll
    for (int u = 0; u < 8; ++u)
        areg[u] = *(const float4*)(src + (size_t)(fr + u * 16) * 768 + fseg * 4);

    for (int it = 0; it < 12; ++it) {
        const int buf = it & 1;
        const uint32_t Ao = 2048 + buf * 16384;
        // store prefetched A regs -> smem (bf16, SW128)
        #pragma unroll
        for (int u = 0; u < 8; ++u) {
            __nv_bfloat162 lo = __floats2bfloat162_rn(areg[u].x, areg[u].y);
            __nv_bfloat162 hi = __floats2bfloat162_rn(areg[u].z, areg[u].w);
            uint2 pk; pk.x = *(uint32_t*)&lo; pk.y = *(uint32_t*)&hi;
            *(uint2*)(smem + Ao + sw128((uint32_t)((fr + u * 16) * 128 + fseg * 8))) = pk;
        }
        CP_WAIT0();            // B(it) landed
        __syncthreads();       // A stores + B visible to all; all MMA(it-1) reads done
        if (it < 11) {
            // stream B(it+1) into the other buffer (overlaps with MMA below)
            uint32_t bdst = sb + 34816 + (buf ^ 1) * 16384;
            const unsigned char* bsrc = g_Wsw + (size_t)(it + 1) * 16384;
            #pragma unroll
            for (int u = 0; u < 4; ++u)
                CP_ASYNC16(bdst + (tid + u * 256) * 16, bsrc + (size_t)(tid + u * 256) * 16);
            CP_COMMIT();
            // prefetch A(it+1) into registers (LDG latency hidden by MMA)
            #pragma unroll
            for (int u = 0; u < 8; ++u)
                areg[u] = *(const float4*)(src + (size_t)(fr + u * 16) * 768 + (it + 1) * 64 + fseg * 4);
        }
        // MMA on buf
        const uint32_t Ab = sb + Ao, Bb = sb + 34816 + buf * 16384;
        #pragma unroll
        for (int ks = 0; ks < 4; ++ks) {
            const int lseg = (ks * 2 + lhalf) * 16;
            uint32_t af[2][4];
            #pragma unroll
            for (int mi = 0; mi < 2; ++mi) {
                int r = wm * 32 + mi * 16 + lrow;
                LDSM_X4(af[mi][0], af[mi][1], af[mi][2], af[mi][3],
                        Ab + sw128((uint32_t)(r * 128 + lseg)));
            }
            uint32_t bf[8][2];
            #pragma unroll
            for (int nb = 0; nb < 4; ++nb) {
                int n = wn * 64 + nb * 16 + lrow;
                uint32_t q0, q1, q2, q3;
                LDSM_X4(q0, q1, q2, q3, Bb + sw128((uint32_t)(n * 128 + lseg)));
                bf[nb * 2][0] = q0; bf[nb * 2][1] = q2;
                bf[nb * 2 + 1][0] = q1; bf[nb * 2 + 1][1] = q3;
            }
            #pragma unroll
            for (int mi = 0; mi < 2; ++mi)
                #pragma unroll
                for (int ni = 0; ni < 8; ++ni)
                    mma16816(c[mi][ni], af[mi], bf[ni][0], bf[ni][1]);
        }
    }

    // ---------------- epilogue: bias, row sum-of-squares, normalize, store ---
    const float* bsm = (const float*)smem;
    float* rowsq = (float*)(smem + 512);
    #pragma unroll
    for (int mi = 0; mi < 2; ++mi)
        #pragma unroll
        for (int rp = 0; rp < 2; ++rp) {
            float s = 0.f;
            #pragma unroll
            for (int ni = 0; ni < 8; ++ni)
                #pragma unroll
                for (int c0 = 0; c0 < 2; ++c0) {
                    int col = wn * 64 + ni * 8 + tg * 2 + c0;
                    float x = c[mi][ni][rp * 2 + c0] + bsm[col];
                    c[mi][ni][rp * 2 + c0] = x;
                    s += x * x;
                }
            s += __shfl_xor_sync(0xFFFFFFFFu, s, 1);
            s += __shfl_xor_sync(0xFFFFFFFFu, s, 2);
            int row = wm * 32 + mi * 16 + gid + rp * 8;
            if (tg == 0) rowsq[wn * 128 + row] = s;
        }
    __syncthreads();

    unsigned char* dst = g_norm + (size_t)t * 32768 + (size_t)wn * 16384;
    #pragma unroll
    for (int mi = 0; mi < 2; ++mi)
        #pragma unroll
        for (int rp = 0; rp < 2; ++rp) {
            int row = wm * 32 + mi * 16 + gid + rp * 8;
            float tot = rowsq[row] + rowsq[128 + row];
            float mf = mask ? (float)mask[r0 + row] : 1.f;
            float sc = mf / fmaxf(sqrtf(tot), 1e-12f);
            #pragma unroll
            for (int ni = 0; ni < 8; ++ni) {
                float x0 = c[mi][ni][rp * 2]     * sc;
                float x1 = c[mi][ni][rp * 2 + 1] * sc;
                __nv_bfloat162 p2 = __floats2bfloat162_rn(x0, x1);
                *(uint32_t*)(dst + sw128((uint32_t)(row * 128 + (ni * 8 + tg * 2) * 2))) =
                    *(uint32_t*)&p2;
            }
        }
}

// ============================ Kernel 2: MaxSim ============================
// grid 256 (= batch*2 pos/neg), block 128 (4 warps, each 32 doc rows).
// Doc tiles double-buffered via cp.async.
// smem: [0..512) reduce buf fp32[4][32],
//       [1024..9216) Q tile: 2 chunks x [32r x 64k] SW128 (4KB each),
//       [9216) doc buf0 (2 x 16KB chunk images), [41984) doc buf1
__global__ void __launch_bounds__(128) k_maxsim(float* __restrict__ out)
{
    extern __shared__ __align__(1024) unsigned char smem[];
    uint32_t sb = smem_u32(smem);
    const int tid = threadIdx.x, wid = tid >> 5, lid = tid & 31;
    const int b = blockIdx.x >> 1, s = blockIdx.x & 1;
    const int tbase = (s ? 544 : 32) + b * 4;

    // prologue: doc tile 0 via cp.async
    {
        uint32_t dd = sb + 9216;
        const unsigned char* ds = g_norm + (size_t)tbase * 32768;
        #pragma unroll
        for (int u = 0; u < 16; ++u)
            CP_ASYNC16(dd + (tid + u * 128) * 16, ds + (size_t)(tid + u * 128) * 16);
        CP_COMMIT();
    }
    // Q slice: tile b>>2, rows (b&3)*32 (row-aligned to 8 -> valid SW128 sub-image)
    {
        const unsigned char* qsrc = g_norm + (size_t)(b >> 2) * 32768 + (size_t)(b & 3) * 4096;
        #pragma unroll
        for (int ch = 0; ch < 2; ++ch) {
            const uint4* sp = (const uint4*)(qsrc + ch * 16384);
            uint4* dp = (uint4*)(smem + 1024 + ch * 4096);
            #pragma unroll
            for (int u = 0; u < 2; ++u) dp[tid + u * 128] = sp[tid + u * 128];
        }
    }

    const int lrow = (lid & 7) + ((lid >> 3) & 1) * 8;
    const int lhalf = lid >> 4;

    float vmax[2][4][4];
    #pragma unroll
    for (int mi = 0; mi < 2; ++mi)
        #pragma unroll
        for (int ni = 0; ni < 4; ++ni)
            #pragma unroll
            for (int r = 0; r < 4; ++r) vmax[mi][ni][r] = -3.0e38f;

    for (int i = 0; i < 4; ++i) {
        const int buf = i & 1;
        CP_WAIT0();
        __syncthreads();
        if (i < 3) {
            uint32_t dd = sb + 9216 + (buf ^ 1) * 32768;
            const unsigned char* ds = g_norm + (size_t)(tbase + i + 1) * 32768;
            #pragma unroll
            for (int u = 0; u < 16; ++u)
                CP_ASYNC16(dd + (tid + u * 128) * 16, ds + (size_t)(tid + u * 128) * 16);
            CP_COMMIT();
        }

        float cc[2][4][4];
        #pragma unroll
        for (int mi = 0; mi < 2; ++mi)
            #pragma unroll
            for (int ni = 0; ni < 4; ++ni)
                #pragma unroll
                for (int r = 0; r < 4; ++r) cc[mi][ni][r] = 0.f;

        const uint32_t Db = sb + 9216 + buf * 32768;
        #pragma unroll
        for (int ks = 0; ks < 8; ++ks) {
            const int chunk = ks >> 2, kk = ks & 3;
            const int lseg = (kk * 2 + lhalf) * 16;
            uint32_t af[2][4];
            #pragma unroll
            for (int mi = 0; mi < 2; ++mi) {
                int r = wid * 32 + mi * 16 + lrow;
                LDSM_X4(af[mi][0], af[mi][1], af[mi][2], af[mi][3],
                        Db + chunk * 16384 + sw128((uint32_t)(r * 128 + lseg)));
            }
            uint32_t bf[4][2];
            #pragma unroll
            for (int nb = 0; nb < 2; ++nb) {
                int n = nb * 16 + lrow;
                uint32_t q0, q1, q2, q3;
                LDSM_X4(q0, q1, q2, q3,
                        sb + 1024 + chunk * 4096 + sw128((uint32_t)(n * 128 + lseg)));
                bf[nb * 2][0] = q0; bf[nb * 2][1] = q2;
                bf[nb * 2 + 1][0] = q1; bf[nb * 2 + 1][1] = q3;
            }
            #pragma unroll
            for (int mi = 0; mi < 2; ++mi)
                #pragma unroll
                for (int ni = 0; ni < 4; ++ni)
                    mma16816(cc[mi][ni], af[mi], bf[ni][0], bf[ni][1]);
        }
        #pragma unroll
        for (int mi = 0; mi < 2; ++mi)
            #pragma unroll
            for (int ni = 0; ni < 4; ++ni)
                #pragma unroll
                for (int r = 0; r < 4; ++r)
                    vmax[mi][ni][r] = fmaxf(vmax[mi][ni][r], cc[mi][ni][r]);
    }

    // per-column max over this warp's 32 doc rows
    float colmax[4][2];
    #pragma unroll
    for (int ni = 0; ni < 4; ++ni)
        #pragma unroll
        for (int c0 = 0; c0 < 2; ++c0) {
            float m = fmaxf(fmaxf(vmax[0][ni][c0], vmax[0][ni][c0 + 2]),
                            fmaxf(vmax[1][ni][c0], vmax[1][ni][c0 + 2]));
            m = fmaxf(m, __shfl_xor_sync(0xFFFFFFFFu, m, 4));
            m = fmaxf(m, __shfl_xor_sync(0xFFFFFFFFu, m, 8));
            m = fmaxf(m, __shfl_xor_sync(0xFFFFFFFFu, m, 16));
            colmax[ni][c0] = m;
        }
    float* red = (float*)smem;
    if (lid < 4) {
        #pragma unroll
        for (int ni = 0; ni < 4; ++ni)
            #pragma unroll
            for (int c0 = 0; c0 < 2; ++c0)
                red[wid * 32 + ni * 8 + lid * 2 + c0] = colmax[ni][c0];
    }
    __syncthreads();
    if (tid < 32) {
        float m = fmaxf(fmaxf(red[tid], red[32 + tid]), fmaxf(red[64 + tid], red[96 + tid]));
        #pragma unroll
        for (int off = 16; off; off >>= 1) m += __shfl_xor_sync(0xFFFFFFFFu, m, off);
        if (tid == 0) out[b * 2 + s] = m;
    }
}

// ============================ launch ============================
extern "C" void kernel_launch(void* const* d_in, const int* in_sizes, int n_in,
                              void* d_out, int out_size) {
    const float* qh  = (const float*)d_in[0];
    const float* pdh = (const float*)d_in[1];
    const float* ndh = (const float*)d_in[2];
    const float* W   = (const float*)d_in[3];
    const float* b   = (const float*)d_in[4];
    const int*   pdm = (const int*)d_in[5];
    const int*   ndm = (const int*)d_in[6];
    float* out = (float*)d_out;

    // dyn smem > 48KB needs an explicit opt-in (host attribute set, not a stream op)
    cudaFuncSetAttribute(k_proj,   cudaFuncAttributeMaxDynamicSharedMemorySize, 67584);
    cudaFuncSetAttribute(k_maxsim, cudaFuncAttributeMaxDynamicSharedMemorySize, 74752);

    k_wprep<<<384, 256>>>(W);
    k_proj<<<1056, 256, 67584>>>(qh, pdh, ndh, b, pdm, ndm);
    k_maxsim<<<256, 128, 74752>>>(out);
}